// round 13
// baseline (speedup 1.0000x reference)
#include <cuda_runtime.h>
#include <cuda_fp16.h>
#include <cstdint>

#define BB 4
#define NN 4096
#define MM 4096
#define DD 256

#define HALF (MM/2)           // 2048 targets per CTA
#define TILE_N 128            // targets per tile
#define NTILES (HALF/TILE_N)  // 16 tiles

// smem: A 256 rows x 512B (swizzled); B 2 bufs x (128 rows x 256B); yn 2x128 f32
#define OFF_A   0
#define A_BYTES (256*512)                 // 131072
#define OFF_B   A_BYTES
#define BHALF   (128*256)                 // 32768 per k-half buffer
#define OFF_YN  (OFF_B + 2*BHALF)         // 196608
#define SMEM_TOTAL (OFF_YN + 1024)        // 197632

// ---------------- device scratch (no allocs allowed) ----------------
__device__ __half g_xh16[BB * NN * DD];   // 8 MB
__device__ __half g_yh16[BB * MM * DD];   // 8 MB
__device__ float g_xnorm[BB * NN];
__device__ float g_ynorm[BB * MM];
__device__ int   g_rowmin[BB * NN];
__device__ int   g_done[BB];

// ---------------- helpers (plain-sm_100-compatible) ----------------
__device__ __forceinline__ uint32_t smem_u32(const void* p) {
    uint32_t a;
    asm("{ .reg .u64 t; cvta.to.shared.u64 t, %1; cvt.u32.u64 %0, t; }"
        : "=r"(a) : "l"(p));
    return a;
}
__device__ __forceinline__ void cp_async16(uint32_t dst, const void* src) {
    asm volatile("cp.async.cg.shared.global [%0], [%1], 16;" :: "r"(dst), "l"(src));
}
__device__ __forceinline__ void cp_async4(uint32_t dst, const void* src) {
    asm volatile("cp.async.ca.shared.global [%0], [%1], 4;" :: "r"(dst), "l"(src));
}
__device__ __forceinline__ void ldm_x4(uint32_t* r, uint32_t addr) {
    asm volatile("ldmatrix.sync.aligned.m8n8.x4.shared.b16 {%0,%1,%2,%3}, [%4];"
        : "=r"(r[0]), "=r"(r[1]), "=r"(r[2]), "=r"(r[3]) : "r"(addr));
}
// fp16-accum HMMA: C/D are 2 x b32 (4 packed halves)
__device__ __forceinline__ void mma16816h(uint32_t* c, const uint32_t* a,
                                          uint32_t b0, uint32_t b1) {
    asm volatile(
        "mma.sync.aligned.m16n8k16.row.col.f16.f16.f16.f16 "
        "{%0,%1}, {%2,%3,%4,%5}, {%6,%7}, {%0,%1};"
        : "+r"(c[0]), "+r"(c[1])
        : "r"(a[0]), "r"(a[1]), "r"(a[2]), "r"(a[3]), "r"(b0), "r"(b1));
}
// First k-step of a tile: D = A*B + 0 (C = zeros, D write-only)
__device__ __forceinline__ void mma16816h_init(uint32_t* c, const uint32_t* a,
                                               uint32_t b0, uint32_t b1) {
    asm volatile(
        "mma.sync.aligned.m16n8k16.row.col.f16.f16.f16.f16 "
        "{%0,%1}, {%2,%3,%4,%5}, {%6,%7}, {%8,%9};"
        : "=r"(c[0]), "=r"(c[1])
        : "r"(a[0]), "r"(a[1]), "r"(a[2]), "r"(a[3]), "r"(b0), "r"(b1),
          "r"(0u), "r"(0u));
}

// One k-step: 8 ldmatrix + 32 MMAs (warp tile 64x64, fp16 acc)
template <bool INIT>
__device__ __forceinline__ void do_kstep(uint32_t acc[4][8][2],
                                         uint32_t aRow, uint32_t bRow,
                                         int ks, int kk,
                                         int hiA, int hiB, int rm) {
    const uint32_t ac = (uint32_t)(((2 * ks + hiA) ^ rm) << 4);
    const uint32_t bc = (uint32_t)(((2 * kk + hiB) ^ rm) << 4);
    uint32_t afr[4][4], bfr[4][4];
#pragma unroll
    for (int mf = 0; mf < 4; ++mf)
        ldm_x4(afr[mf], aRow + (uint32_t)(mf * 16 * 512) + ac);
#pragma unroll
    for (int nf2 = 0; nf2 < 4; ++nf2)
        ldm_x4(bfr[nf2], bRow + (uint32_t)(nf2 * 16 * 256) + bc);
#pragma unroll
    for (int mf = 0; mf < 4; ++mf)
#pragma unroll
        for (int nf2 = 0; nf2 < 4; ++nf2)
#pragma unroll
            for (int g = 0; g < 2; ++g) {
                if (INIT)
                    mma16816h_init(acc[mf][nf2 * 2 + g], afr[mf],
                                   bfr[nf2][g * 2], bfr[nf2][g * 2 + 1]);
                else
                    mma16816h(acc[mf][nf2 * 2 + g], afr[mf],
                              bfr[nf2][g * 2], bfr[nf2][g * 2 + 1]);
            }
}

// ---------------------------------------------------------------------------
// Kernel 1: fp32 -> fp16 + exact fp32 row norms (warp per row); init rowmin.
// ---------------------------------------------------------------------------
__global__ void prep_kernel(const float* __restrict__ src,
                            const float* __restrict__ tgt) {
    int warp = (blockIdx.x * blockDim.x + threadIdx.x) >> 5;
    int lane = threadIdx.x & 31;
    if (blockIdx.x == 0 && threadIdx.x < BB) g_done[threadIdx.x] = 0;
    const int total = BB * NN + BB * MM;
    if (warp >= total) return;

    const float* base; __half* obase; float* onorm; int row;
    bool isx = warp < BB * NN;
    if (isx) { base = src; obase = g_xh16; onorm = g_xnorm; row = warp; }
    else     { base = tgt; obase = g_yh16; onorm = g_ynorm; row = warp - BB * NN; }

    const float4* p = (const float4*)(base + (long long)row * DD);
    float4 v0 = p[2 * lane];
    float4 v1 = p[2 * lane + 1];
    float s = v0.x * v0.x + v0.y * v0.y + v0.z * v0.z + v0.w * v0.w
            + v1.x * v1.x + v1.y * v1.y + v1.z * v1.z + v1.w * v1.w;

    __half2 h0 = __floats2half2_rn(v0.x, v0.y);
    __half2 h1 = __floats2half2_rn(v0.z, v0.w);
    __half2 h2 = __floats2half2_rn(v1.x, v1.y);
    __half2 h3 = __floats2half2_rn(v1.z, v1.w);
    uint4 o;
    o.x = *(uint32_t*)&h0; o.y = *(uint32_t*)&h1;
    o.z = *(uint32_t*)&h2; o.w = *(uint32_t*)&h3;
    ((uint4*)(obase + (long long)row * DD))[lane] = o;

#pragma unroll
    for (int off = 16; off > 0; off >>= 1) s += __shfl_down_sync(0xffffffffu, s, off);
    if (lane == 0) {
        onorm[row] = s;
        if (isx) g_rowmin[row] = 0x7F800000;
    }
}

// ---------------------------------------------------------------------------
// Kernel 2: fp16 HMMA GEMM + row-min. Warp tile 64x64 (4Mx2N warps).
// CTA = 256 rows x 2048 targets, 16 tiles of 128 targets, B pipelined at
// k-half granularity. fp16 accumulators (64 regs) free registers for
// cross-kstep fragment pipelining. grid (32,4).
// ---------------------------------------------------------------------------
__global__ __launch_bounds__(256, 1)
void mincost_kernel(float* __restrict__ out) {
    extern __shared__ __align__(1024) char smem[];
    __shared__ int ticket_s;
    __shared__ float red_s[8];
    uint32_t sb = smem_u32(smem);
    const int tid  = threadIdx.x;
    const int w    = tid >> 5;
    const int lane = tid & 31;
    const int b    = blockIdx.y;
    const int mgrp = blockIdx.x >> 1;
    const int half = blockIdx.x & 1;
    const int base_row = mgrp * 256;
    const int warpM = w >> 1;
    const int warpN = w & 1;
    const int groupID = lane >> 2;
    const int tig     = lane & 3;

    const __half*  xa  = g_xh16 + ((long long)b * NN + base_row) * DD;
    const __half*  yb  = g_yh16 + ((long long)b * MM + half * HALF) * DD;
    const float*   yng = g_ynorm + b * MM + half * HALF;

    // ---- initial loads: A (swizzled) + B k-half 0 of tile 0 + yn[0] ----
#pragma unroll
    for (int u = 0; u < 32; ++u) {
        int c = tid + 256 * u;
        int r = c >> 5, c16 = c & 31;
        cp_async16(sb + OFF_A + r * 512 + ((c16 ^ (r & 7)) << 4),
                   xa + r * DD + c16 * 8);
    }
#pragma unroll
    for (int u = 0; u < 8; ++u) {
        int c = tid + 256 * u;
        int r = c >> 4, c16 = c & 15;
        cp_async16(sb + OFF_B + r * 256 + ((c16 ^ (r & 7)) << 4),
                   yb + r * DD + c16 * 8);
    }
    if (tid < TILE_N) cp_async4(sb + OFF_YN + tid * 4, yng + tid);
    asm volatile("cp.async.commit_group;");

    const int rowA = warpM * 64 + (lane & 15);
    const int hiA  = lane >> 4;
    const int rowB = warpN * 64 + (lane & 7) + ((lane >> 4) & 1) * 8;
    const int hiB  = (lane >> 3) & 1;
    const int rm   = lane & 7;
    const uint32_t aRow  = sb + OFF_A + (uint32_t)rowA * 512;
    const uint32_t bRow0 = sb + OFF_B + (uint32_t)rowB * 256;           // buf0
    const uint32_t bRow1 = sb + OFF_B + BHALF + (uint32_t)rowB * 256;   // buf1

    float rmin[8];
#pragma unroll
    for (int i = 0; i < 8; ++i) rmin[i] = 3.4e38f;

    uint32_t acc[4][8][2];

    for (int jt = 0; jt < NTILES; ++jt) {
        // ================= k-half 0 (buf0, A ks 0..7) =================
        asm volatile("cp.async.wait_group 0;");
        __syncthreads();
        // prefetch k-half 1 of this tile into buf1
        {
            const __half* yt = yb + (long long)jt * TILE_N * DD + 128;
#pragma unroll
            for (int u = 0; u < 8; ++u) {
                int c = tid + 256 * u;
                int r = c >> 4, c16 = c & 15;
                cp_async16(sb + OFF_B + BHALF + r * 256 + ((c16 ^ (r & 7)) << 4),
                           yt + r * DD + c16 * 8);
            }
            asm volatile("cp.async.commit_group;");
        }
        do_kstep<true>(acc, aRow, bRow0, 0, 0, hiA, hiB, rm);
#pragma unroll
        for (int kk = 1; kk < 8; ++kk)
            do_kstep<false>(acc, aRow, bRow0, kk, kk, hiA, hiB, rm);

        // ================= k-half 1 (buf1, A ks 8..15) =================
        asm volatile("cp.async.wait_group 0;");
        __syncthreads();
        // prefetch k-half 0 of next tile into buf0 (+ its yn)
        if (jt + 1 < NTILES) {
            const __half* yt = yb + (long long)(jt + 1) * TILE_N * DD;
#pragma unroll
            for (int u = 0; u < 8; ++u) {
                int c = tid + 256 * u;
                int r = c >> 4, c16 = c & 15;
                cp_async16(sb + OFF_B + r * 256 + ((c16 ^ (r & 7)) << 4),
                           yt + r * DD + c16 * 8);
            }
            if (tid < TILE_N)
                cp_async4(sb + OFF_YN + ((jt + 1) & 1) * 512 + tid * 4,
                          yng + (jt + 1) * TILE_N + tid);
            asm volatile("cp.async.commit_group;");
        }
#pragma unroll
        for (int kk = 0; kk < 8; ++kk)
            do_kstep<false>(acc, aRow, bRow1, 8 + kk, kk, hiA, hiB, rm);

        // ---- fold tile into running per-thread row minima (fp32 math) ----
        const float* ynp = (const float*)(smem + OFF_YN + (jt & 1) * 512);
#pragma unroll
        for (int nf = 0; nf < 8; ++nf) {
            float y0 = ynp[warpN * 64 + nf * 8 + tig * 2];
            float y1 = ynp[warpN * 64 + nf * 8 + tig * 2 + 1];
#pragma unroll
            for (int mf = 0; mf < 4; ++mf) {
                float2 p0 = __half22float2(*(const __half2*)&acc[mf][nf][0]);
                float2 p1 = __half22float2(*(const __half2*)&acc[mf][nf][1]);
                rmin[mf * 2] = fminf(rmin[mf * 2],
                    fminf(fmaf(-2.0f, p0.x, y0), fmaf(-2.0f, p0.y, y1)));
                rmin[mf * 2 + 1] = fminf(rmin[mf * 2 + 1],
                    fminf(fmaf(-2.0f, p1.x, y0), fmaf(-2.0f, p1.y, y1)));
            }
        }
    }

    // reduce over the 4 threads sharing each row, then global atomicMin
#pragma unroll
    for (int i = 0; i < 8; ++i) {
        rmin[i] = fminf(rmin[i], __shfl_xor_sync(0xffffffffu, rmin[i], 1));
        rmin[i] = fminf(rmin[i], __shfl_xor_sync(0xffffffffu, rmin[i], 2));
    }
    if (tig == 0) {
#pragma unroll
        for (int mf = 0; mf < 4; ++mf)
#pragma unroll
            for (int h8 = 0; h8 < 2; ++h8) {
                int row = base_row + warpM * 64 + mf * 16 + h8 * 8 + groupID;
                float xn = g_xnorm[b * NN + row];
                float cand = fmaxf(xn + rmin[mf * 2 + h8], 0.0f);
                atomicMin(&g_rowmin[b * NN + row], __float_as_int(cand));
            }
    }

    // ----- ticketed tail: last CTA of this batch computes the batch mean -----
    __threadfence();
    __syncthreads();
    if (tid == 0) ticket_s = atomicAdd(&g_done[b], 1);
    __syncthreads();
    if (ticket_s == 2 * (NN / 256) - 1) {
        __threadfence();
        const int4* p = (const int4*)(g_rowmin + b * NN);
        float s = 0.0f;
        for (int i = tid; i < NN / 4; i += 256) {
            int4 v = p[i];
            s += __int_as_float(v.x) + __int_as_float(v.y)
               + __int_as_float(v.z) + __int_as_float(v.w);
        }
#pragma unroll
        for (int o = 16; o > 0; o >>= 1) s += __shfl_down_sync(0xffffffffu, s, o);
        if (lane == 0) red_s[w] = s;
        __syncthreads();
        if (tid == 0) {
            float t = 0.0f;
#pragma unroll
            for (int wv = 0; wv < 8; ++wv) t += red_s[wv];
            out[b] = t * (1.0f / (float)NN);
        }
    }
}

// ---------------------------------------------------------------------------
extern "C" void kernel_launch(void* const* d_in, const int* in_sizes, int n_in,
                              void* d_out, int out_size) {
    const float* src = (const float*)d_in[0];
    const float* tgt = (const float*)d_in[1];
    float* out = (float*)d_out;

    cudaFuncSetAttribute(mincost_kernel,
                         cudaFuncAttributeMaxDynamicSharedMemorySize, SMEM_TOTAL);

    prep_kernel<<<BB * (NN + MM) / 8, 256>>>(src, tgt);
    mincost_kernel<<<dim3(32, 4), 256, SMEM_TOTAL>>>(out);
}

// round 15
// speedup vs baseline: 1.0607x; 1.0607x over previous
#include <cuda_runtime.h>
#include <cuda_fp16.h>
#include <cstdint>

#define BB 4
#define NN 4096
#define MM 4096
#define DD 256

#define HALF (MM/2)           // 2048 targets per CTA
#define TILE_N 128            // targets per tile
#define NTILES (HALF/TILE_N)  // 16 tiles

// smem: A 256 rows x 512B (swizzled); B 2 bufs x (128 rows x 256B); yn 2x128 fp16
#define OFF_A   0
#define A_BYTES (256*512)                 // 131072
#define OFF_B   A_BYTES
#define BHALF   (128*256)                 // 32768 per k-half buffer
#define OFF_YN  (OFF_B + 2*BHALF)         // 196608
#define SMEM_TOTAL (OFF_YN + 1024)        // 197632

// ---------------- device scratch (no allocs allowed) ----------------
__device__ __half g_xh16[BB * NN * DD];   // 8 MB
__device__ __half g_yh16[BB * MM * DD];   // 8 MB
__device__ float  g_xnorm[BB * NN];
__device__ __half g_ynorm_h[BB * MM];
__device__ int    g_rowmin[BB * NN];
__device__ int    g_done[BB];

// ---------------- helpers (plain-sm_100-compatible) ----------------
__device__ __forceinline__ uint32_t smem_u32(const void* p) {
    uint32_t a;
    asm("{ .reg .u64 t; cvta.to.shared.u64 t, %1; cvt.u32.u64 %0, t; }"
        : "=r"(a) : "l"(p));
    return a;
}
__device__ __forceinline__ void cp_async16(uint32_t dst, const void* src) {
    asm volatile("cp.async.cg.shared.global [%0], [%1], 16;" :: "r"(dst), "l"(src));
}
__device__ __forceinline__ void cp_async4(uint32_t dst, const void* src) {
    asm volatile("cp.async.ca.shared.global [%0], [%1], 4;" :: "r"(dst), "l"(src));
}
__device__ __forceinline__ void ldm_x4(uint32_t* r, uint32_t addr) {
    asm volatile("ldmatrix.sync.aligned.m8n8.x4.shared.b16 {%0,%1,%2,%3}, [%4];"
        : "=r"(r[0]), "=r"(r[1]), "=r"(r[2]), "=r"(r[3]) : "r"(addr));
}
// fp16-accum HMMA: C/D are 2 x b32 (4 packed halves)
__device__ __forceinline__ void mma16816h(uint32_t* c, const uint32_t* a,
                                          uint32_t b0, uint32_t b1) {
    asm volatile(
        "mma.sync.aligned.m16n8k16.row.col.f16.f16.f16.f16 "
        "{%0,%1}, {%2,%3,%4,%5}, {%6,%7}, {%0,%1};"
        : "+r"(c[0]), "+r"(c[1])
        : "r"(a[0]), "r"(a[1]), "r"(a[2]), "r"(a[3]), "r"(b0), "r"(b1));
}
// First k-step of a tile: D = A*B + 0 (C = zeros, D write-only)
__device__ __forceinline__ void mma16816h_init(uint32_t* c, const uint32_t* a,
                                               uint32_t b0, uint32_t b1) {
    asm volatile(
        "mma.sync.aligned.m16n8k16.row.col.f16.f16.f16.f16 "
        "{%0,%1}, {%2,%3,%4,%5}, {%6,%7}, {%8,%9};"
        : "=r"(c[0]), "=r"(c[1])
        : "r"(a[0]), "r"(a[1]), "r"(a[2]), "r"(a[3]), "r"(b0), "r"(b1),
          "r"(0u), "r"(0u));
}

// One k-step: 8 ldmatrix + 32 MMAs (warp tile 64x64, fp16 acc)
template <bool INIT>
__device__ __forceinline__ void do_kstep(uint32_t acc[4][8][2],
                                         uint32_t aRow, uint32_t bRow,
                                         int ks, int kk,
                                         int hiA, int hiB, int rm) {
    const uint32_t ac = (uint32_t)(((2 * ks + hiA) ^ rm) << 4);
    const uint32_t bc = (uint32_t)(((2 * kk + hiB) ^ rm) << 4);
    uint32_t afr[4][4], bfr[4][4];
#pragma unroll
    for (int mf = 0; mf < 4; ++mf)
        ldm_x4(afr[mf], aRow + (uint32_t)(mf * 16 * 512) + ac);
#pragma unroll
    for (int nf2 = 0; nf2 < 4; ++nf2)
        ldm_x4(bfr[nf2], bRow + (uint32_t)(nf2 * 16 * 256) + bc);
#pragma unroll
    for (int mf = 0; mf < 4; ++mf)
#pragma unroll
        for (int nf2 = 0; nf2 < 4; ++nf2)
#pragma unroll
            for (int g = 0; g < 2; ++g) {
                if (INIT)
                    mma16816h_init(acc[mf][nf2 * 2 + g], afr[mf],
                                   bfr[nf2][g * 2], bfr[nf2][g * 2 + 1]);
                else
                    mma16816h(acc[mf][nf2 * 2 + g], afr[mf],
                              bfr[nf2][g * 2], bfr[nf2][g * 2 + 1]);
            }
}

// ---------------------------------------------------------------------------
// Kernel 1: fp32 -> fp16 + row norms (x: fp32 norm; y: fp16 norm); init rowmin.
// ---------------------------------------------------------------------------
__global__ void prep_kernel(const float* __restrict__ src,
                            const float* __restrict__ tgt) {
    int warp = (blockIdx.x * blockDim.x + threadIdx.x) >> 5;
    int lane = threadIdx.x & 31;
    if (blockIdx.x == 0 && threadIdx.x < BB) g_done[threadIdx.x] = 0;
    const int total = BB * NN + BB * MM;
    if (warp >= total) return;

    const float* base; __half* obase; int row;
    bool isx = warp < BB * NN;
    if (isx) { base = src; obase = g_xh16; row = warp; }
    else     { base = tgt; obase = g_yh16; row = warp - BB * NN; }

    const float4* p = (const float4*)(base + (long long)row * DD);
    float4 v0 = p[2 * lane];
    float4 v1 = p[2 * lane + 1];
    float s = v0.x * v0.x + v0.y * v0.y + v0.z * v0.z + v0.w * v0.w
            + v1.x * v1.x + v1.y * v1.y + v1.z * v1.z + v1.w * v1.w;

    __half2 h0 = __floats2half2_rn(v0.x, v0.y);
    __half2 h1 = __floats2half2_rn(v0.z, v0.w);
    __half2 h2 = __floats2half2_rn(v1.x, v1.y);
    __half2 h3 = __floats2half2_rn(v1.z, v1.w);
    uint4 o;
    o.x = *(uint32_t*)&h0; o.y = *(uint32_t*)&h1;
    o.z = *(uint32_t*)&h2; o.w = *(uint32_t*)&h3;
    ((uint4*)(obase + (long long)row * DD))[lane] = o;

#pragma unroll
    for (int off = 16; off > 0; off >>= 1) s += __shfl_down_sync(0xffffffffu, s, off);
    if (lane == 0) {
        if (isx) { g_xnorm[row] = s; g_rowmin[row] = 0x7F800000; }
        else     { g_ynorm_h[row] = __float2half_rn(s); }
    }
}

// ---------------------------------------------------------------------------
// Kernel 2: fp16 HMMA GEMM + row-min with packed half2 fold.
// Warp tile 64x64 (4Mx2N warps). CTA = 256 rows x 2048 targets, 16 tiles,
// B pipelined at k-half granularity. grid (32,4).
// ---------------------------------------------------------------------------
__global__ __launch_bounds__(256, 1)
void mincost_kernel(float* __restrict__ out) {
    extern __shared__ __align__(1024) char smem[];
    __shared__ int ticket_s;
    __shared__ float red_s[8];
    uint32_t sb = smem_u32(smem);
    const int tid  = threadIdx.x;
    const int w    = tid >> 5;
    const int lane = tid & 31;
    const int b    = blockIdx.y;
    const int mgrp = blockIdx.x >> 1;
    const int half = blockIdx.x & 1;
    const int base_row = mgrp * 256;
    const int warpM = w >> 1;
    const int warpN = w & 1;
    const int groupID = lane >> 2;
    const int tig     = lane & 3;

    const __half*  xa  = g_xh16 + ((long long)b * NN + base_row) * DD;
    const __half*  yb  = g_yh16 + ((long long)b * MM + half * HALF) * DD;
    const __half*  yng = g_ynorm_h + b * MM + half * HALF;

    // ---- initial loads: A (swizzled) + B k-half 0 of tile 0 + yn[0] ----
#pragma unroll
    for (int u = 0; u < 32; ++u) {
        int c = tid + 256 * u;
        int r = c >> 5, c16 = c & 31;
        cp_async16(sb + OFF_A + r * 512 + ((c16 ^ (r & 7)) << 4),
                   xa + r * DD + c16 * 8);
    }
#pragma unroll
    for (int u = 0; u < 8; ++u) {
        int c = tid + 256 * u;
        int r = c >> 4, c16 = c & 15;
        cp_async16(sb + OFF_B + r * 256 + ((c16 ^ (r & 7)) << 4),
                   yb + r * DD + c16 * 8);
    }
    if (tid < 64) cp_async4(sb + OFF_YN + tid * 4, yng + tid * 2);
    asm volatile("cp.async.commit_group;");

    const int rowA = warpM * 64 + (lane & 15);
    const int hiA  = lane >> 4;
    const int rowB = warpN * 64 + (lane & 7) + ((lane >> 4) & 1) * 8;
    const int hiB  = (lane >> 3) & 1;
    const int rm   = lane & 7;
    const uint32_t aRow  = sb + OFF_A + (uint32_t)rowA * 512;
    const uint32_t bRow0 = sb + OFF_B + (uint32_t)rowB * 256;           // buf0
    const uint32_t bRow1 = sb + OFF_B + BHALF + (uint32_t)rowB * 256;   // buf1

    const __half2 m2 = __float2half2_rn(-2.0f);
    __half2 rmin2[8];
#pragma unroll
    for (int i = 0; i < 8; ++i) rmin2[i] = __float2half2_rn(65504.0f);

    uint32_t acc[4][8][2];

    for (int jt = 0; jt < NTILES; ++jt) {
        // ================= k-half 0 (buf0, A ks 0..7) =================
        asm volatile("cp.async.wait_group 0;");
        __syncthreads();
        // prefetch k-half 1 of this tile into buf1
        {
            const __half* yt = yb + (long long)jt * TILE_N * DD + 128;
#pragma unroll
            for (int u = 0; u < 8; ++u) {
                int c = tid + 256 * u;
                int r = c >> 4, c16 = c & 15;
                cp_async16(sb + OFF_B + BHALF + r * 256 + ((c16 ^ (r & 7)) << 4),
                           yt + r * DD + c16 * 8);
            }
            asm volatile("cp.async.commit_group;");
        }
        do_kstep<true>(acc, aRow, bRow0, 0, 0, hiA, hiB, rm);
#pragma unroll
        for (int kk = 1; kk < 8; ++kk)
            do_kstep<false>(acc, aRow, bRow0, kk, kk, hiA, hiB, rm);

        // ================= k-half 1 (buf1, A ks 8..15) =================
        asm volatile("cp.async.wait_group 0;");
        __syncthreads();
        // prefetch k-half 0 of next tile into buf0 (+ its yn)
        if (jt + 1 < NTILES) {
            const __half* yt = yb + (long long)(jt + 1) * TILE_N * DD;
#pragma unroll
            for (int u = 0; u < 8; ++u) {
                int c = tid + 256 * u;
                int r = c >> 4, c16 = c & 15;
                cp_async16(sb + OFF_B + r * 256 + ((c16 ^ (r & 7)) << 4),
                           yt + r * DD + c16 * 8);
            }
            if (tid < 64)
                cp_async4(sb + OFF_YN + ((jt + 1) & 1) * 256 + tid * 4,
                          yng + (jt + 1) * TILE_N + tid * 2);
            asm volatile("cp.async.commit_group;");
        }
#pragma unroll
        for (int kk = 0; kk < 8; ++kk)
            do_kstep<false>(acc, aRow, bRow1, 8 + kk, kk, hiA, hiB, rm);

        // ---- packed half2 fold: lanes = the two column classes of a row ----
        const __half2* ynp2 =
            (const __half2*)(smem + OFF_YN + (jt & 1) * 256);
#pragma unroll
        for (int nf = 0; nf < 8; ++nf) {
            __half2 yn2 = ynp2[warpN * 32 + nf * 4 + tig];
#pragma unroll
            for (int mf = 0; mf < 4; ++mf) {
                __half2 c0 = __hfma2(*(const __half2*)&acc[mf][nf][0], m2, yn2);
                __half2 c1 = __hfma2(*(const __half2*)&acc[mf][nf][1], m2, yn2);
                rmin2[mf * 2]     = __hmin2(rmin2[mf * 2], c0);
                rmin2[mf * 2 + 1] = __hmin2(rmin2[mf * 2 + 1], c1);
            }
        }
    }

    // merge packed lanes, reduce over the 4 threads sharing each row
    float rmin[8];
#pragma unroll
    for (int i = 0; i < 8; ++i) {
        rmin[i] = fminf(__low2float(rmin2[i]), __high2float(rmin2[i]));
        rmin[i] = fminf(rmin[i], __shfl_xor_sync(0xffffffffu, rmin[i], 1));
        rmin[i] = fminf(rmin[i], __shfl_xor_sync(0xffffffffu, rmin[i], 2));
    }
    if (tig == 0) {
#pragma unroll
        for (int mf = 0; mf < 4; ++mf)
#pragma unroll
            for (int h8 = 0; h8 < 2; ++h8) {
                int row = base_row + warpM * 64 + mf * 16 + h8 * 8 + groupID;
                float xn = g_xnorm[b * NN + row];
                float cand = fmaxf(xn + rmin[mf * 2 + h8], 0.0f);
                atomicMin(&g_rowmin[b * NN + row], __float_as_int(cand));
            }
    }

    // ----- ticketed tail: last CTA of this batch computes the batch mean -----
    __threadfence();
    __syncthreads();
    if (tid == 0) ticket_s = atomicAdd(&g_done[b], 1);
    __syncthreads();
    if (ticket_s == 2 * (NN / 256) - 1) {
        __threadfence();
        const int4* p = (const int4*)(g_rowmin + b * NN);
        float s = 0.0f;
        for (int i = tid; i < NN / 4; i += 256) {
            int4 v = p[i];
            s += __int_as_float(v.x) + __int_as_float(v.y)
               + __int_as_float(v.z) + __int_as_float(v.w);
        }
#pragma unroll
        for (int o = 16; o > 0; o >>= 1) s += __shfl_down_sync(0xffffffffu, s, o);
        if (lane == 0) red_s[w] = s;
        __syncthreads();
        if (tid == 0) {
            float t = 0.0f;
#pragma unroll
            for (int wv = 0; wv < 8; ++wv) t += red_s[wv];
            out[b] = t * (1.0f / (float)NN);
        }
    }
}

// ---------------------------------------------------------------------------
extern "C" void kernel_launch(void* const* d_in, const int* in_sizes, int n_in,
                              void* d_out, int out_size) {
    const float* src = (const float*)d_in[0];
    const float* tgt = (const float*)d_in[1];
    float* out = (float*)d_out;

    cudaFuncSetAttribute(mincost_kernel,
                         cudaFuncAttributeMaxDynamicSharedMemorySize, SMEM_TOTAL);

    prep_kernel<<<BB * (NN + MM) / 8, 256>>>(src, tgt);
    mincost_kernel<<<dim3(32, 4), 256, SMEM_TOTAL>>>(out);
}